// round 14
// baseline (speedup 1.0000x reference)
#include <cuda_runtime.h>

namespace {
constexpr int S_TOT   = 22743;           // 3*(76^2 + 38^2 + 19^2)
constexpr int S1      = 17328;           // 76*76*3
constexpr int C       = 85;
constexpr int LEN     = S1 * C;          // 1,472,880 dense floats per batch
constexpr int STRIDEB = S_TOT * C;       // 1,933,155 floats per batch
constexpr int V4U     = (LEN - 3) / 4;   // 368,219 uniform float4s per batch
constexpr int OFF4_D  = (STRIDEB + 1) / 4;  // 483,289 (pad delta +1)
constexpr int OFF4_D3 = (STRIDEB - 3) / 4;  // 483,288 (pad delta -3, b%4==3)
constexpr int TPB     = 256;
constexpr int MINBPM  = 4;               // 64 regs/thread budget -> real MLP=8
constexpr int MAXNB   = 4096;
constexpr unsigned PRIM_BYTES = 116u << 20;  // 116 MB of tg pinned evict_last
}

__device__ float    g_partials[MAXNB * 5];
__device__ unsigned g_count = 0;

// Range policy: tg[0, prim) -> evict_last, tg[prim, tot) -> evict_first
__device__ __forceinline__ unsigned long long mk_policy_range(const void* base,
                                                              unsigned prim,
                                                              unsigned tot) {
    unsigned long long pol;
    asm("createpolicy.range.global.L2::evict_last.L2::evict_first.b64 %0, [%1], %2, %3;"
        : "=l"(pol) : "l"(base), "r"(prim), "r"(tot));
    return pol;
}

__device__ __forceinline__ float4 ld_el4(const float4* p, unsigned long long pol) {
    float4 v;
    asm("ld.global.nc.L2::cache_hint.v4.f32 {%0,%1,%2,%3}, [%4], %5;"
        : "=f"(v.x), "=f"(v.y), "=f"(v.z), "=f"(v.w) : "l"(p), "l"(pol));
    return v;
}
__device__ __forceinline__ float ld_el1(const float* p, unsigned long long pol) {
    float v;
    asm("ld.global.nc.L2::cache_hint.f32 %0, [%1], %2;" : "=f"(v) : "l"(p), "l"(pol));
    return v;
}

// BCE in log2 units: returns t*(lg2 p - lg2 q) + lg2 q ; final loss = -ln2 * sum
__device__ __forceinline__ float bce_l2(float p, float t) {
    float lp = __log2f(p);
    float lq = __log2f(1.0f - p);
    return fmaf(t, lp - lq, lq);
}

__device__ __forceinline__ float bce4_l2(float4 p, float4 t) {
    float b0 = bce_l2(p.x, t.x);
    float b1 = bce_l2(p.y, t.y);
    float b2 = bce_l2(p.z, t.z);
    float b3 = bce_l2(p.w, t.w);
    return (b0 + b1) + (b2 + b3);
}

__global__ __launch_bounds__(TPB, MINBPM)
void yolo_fused(const float* __restrict__ x,
                const float* __restrict__ tg,
                int B, float inv_obj_div,
                unsigned tg_bytes,
                float* __restrict__ out) {
    const int gtid = blockIdx.x * TPB + threadIdx.x;
    const int NT   = gridDim.x * TPB;
    const int W4   = B * V4U;
    const int rows = B * S_TOT;
    const unsigned long long POL = mk_policy_range(tg, PRIM_BYTES, tg_bytes);

    const float4* __restrict__ x4 = (const float4*)x;
    const float4* __restrict__ t4 = (const float4*)tg;

    float a_obj = 0.f, a_xy = 0.f, a_wh = 0.f, a_cls = 0.f, a_cnt = 0.f;

    // ── Prefetch first two Pass-B probes (held across Pass A) ──
    const int r0 = gtid;
    const int r1 = gtid + NT;
    float pf0 = ld_el1(tg + r0 * C + 4, POL);
    float pf1 = (r1 < rows) ? ld_el1(tg + r1 * C + 4, POL) : 0.0f;

    // ── Pass A: flat dense-slab BCE, batch carried incrementally (no div) ──
    int v = gtid, b = 0, off4 = 0;

#define YSTEP()                                                    \
    do {                                                           \
        v += NT;                                                   \
        if (v >= V4U) {                                            \
            v -= V4U;                                              \
            off4 += ((b & 3) == 3) ? OFF4_D3 : OFF4_D;             \
            ++b;                                                   \
        }                                                          \
    } while (0)

    int w = gtid;
    for (; w + 3 * NT < W4; w += 4 * NT) {
        int a0 = off4 + v; YSTEP();
        int a1 = off4 + v; YSTEP();
        int a2 = off4 + v; YSTEP();
        int a3 = off4 + v; YSTEP();
        // x: streaming/evict-first; tg: range policy (116MB pinned evict_last)
        float4 p0 = __ldcs(x4 + a0), q0 = ld_el4(t4 + a0, POL);
        float4 p1 = __ldcs(x4 + a1), q1 = ld_el4(t4 + a1, POL);
        float4 p2 = __ldcs(x4 + a2), q2 = ld_el4(t4 + a2, POL);
        float4 p3 = __ldcs(x4 + a3), q3 = ld_el4(t4 + a3, POL);
        a_obj += bce4_l2(p0, q0) + bce4_l2(p1, q1);
        a_obj += bce4_l2(p2, q2) + bce4_l2(p3, q3);
    }
    for (; w < W4; w += NT) {
        int a0 = off4 + v; YSTEP();
        a_obj += bce4_l2(__ldcs(x4 + a0), ld_el4(t4 + a0, POL));
    }
#undef YSTEP

    // Third-row probe: issued now, consumed after leftover handling.
    const int r2 = gtid + 2 * NT;
    float pf2 = (r2 < rows) ? ld_el1(tg + r2 * C + 4, POL) : 0.0f;

    // leftover scalars: exactly 4 per batch (alignment head + tail remainder)
    if (gtid < 4 * B) {
        int bb  = gtid >> 2, j = gtid & 3;
        int pad = bb & 3;
        int base = bb * STRIDEB;
        int idx = (j < pad) ? (base + j)
                            : (base + pad + 4 * V4U + (j - pad));
        a_obj += bce_l2(x[idx], ld_el1(tg + idx, POL));
    }

    // ── Pass B: gated xy/wh/cls terms ──
    {
        if (pf0 > 0.0f) {
            const int rb = r0 * C;
            a_xy  += bce_l2(__ldg(x + rb + 0), ld_el1(tg + rb + 0, POL))
                   + bce_l2(__ldg(x + rb + 1), ld_el1(tg + rb + 1, POL));
            a_wh  += bce_l2(__ldg(x + rb + 2), ld_el1(tg + rb + 2, POL))
                   + bce_l2(__ldg(x + rb + 3), ld_el1(tg + rb + 3, POL));
            a_cls += bce_l2(__ldg(x + rb + 4), pf0);
            a_cnt += 1.0f;
        }
        if (r1 < rows && pf1 > 0.0f) {
            const int rb = r1 * C;
            a_xy  += bce_l2(__ldg(x + rb + 0), ld_el1(tg + rb + 0, POL))
                   + bce_l2(__ldg(x + rb + 1), ld_el1(tg + rb + 1, POL));
            a_wh  += bce_l2(__ldg(x + rb + 2), ld_el1(tg + rb + 2, POL))
                   + bce_l2(__ldg(x + rb + 3), ld_el1(tg + rb + 3, POL));
            a_cls += bce_l2(__ldg(x + rb + 4), pf1);
            a_cnt += 1.0f;
        }
        if (r2 < rows && pf2 > 0.0f) {
            const int rb = r2 * C;
            a_xy  += bce_l2(__ldg(x + rb + 0), ld_el1(tg + rb + 0, POL))
                   + bce_l2(__ldg(x + rb + 1), ld_el1(tg + rb + 1, POL));
            a_wh  += bce_l2(__ldg(x + rb + 2), ld_el1(tg + rb + 2, POL))
                   + bce_l2(__ldg(x + rb + 3), ld_el1(tg + rb + 3, POL));
            a_cls += bce_l2(__ldg(x + rb + 4), pf2);
            a_cnt += 1.0f;
        }
        // safety remainder (only if the grid ended up tiny)
        for (int r = gtid + 3 * NT; r < rows; r += NT) {
            const int rb = r * C;
            float t4v = ld_el1(tg + rb + 4, POL);
            if (t4v > 0.0f) {
                a_xy  += bce_l2(x[rb + 0], ld_el1(tg + rb + 0, POL))
                       + bce_l2(x[rb + 1], ld_el1(tg + rb + 1, POL));
                a_wh  += bce_l2(x[rb + 2], ld_el1(tg + rb + 2, POL))
                       + bce_l2(x[rb + 3], ld_el1(tg + rb + 3, POL));
                a_cls += bce_l2(x[rb + 4], t4v);
                a_cnt += 1.0f;
            }
        }
    }

    // ── block reduction (5 scalars) ──
    const int lane = threadIdx.x & 31;
    const int wid  = threadIdx.x >> 5;
    #pragma unroll
    for (int off = 16; off; off >>= 1) {
        a_obj += __shfl_xor_sync(0xffffffffu, a_obj, off);
        a_xy  += __shfl_xor_sync(0xffffffffu, a_xy,  off);
        a_wh  += __shfl_xor_sync(0xffffffffu, a_wh,  off);
        a_cls += __shfl_xor_sync(0xffffffffu, a_cls, off);
        a_cnt += __shfl_xor_sync(0xffffffffu, a_cnt, off);
    }
    __shared__ float sm[TPB / 32][5];
    if (lane == 0) {
        sm[wid][0] = a_obj; sm[wid][1] = a_xy; sm[wid][2] = a_wh;
        sm[wid][3] = a_cls; sm[wid][4] = a_cnt;
    }
    __syncthreads();
    if (threadIdx.x < 32) {
        #pragma unroll
        for (int k = 0; k < 5; k++) {
            float vv = (lane < TPB / 32) ? sm[lane][k] : 0.0f;
            #pragma unroll
            for (int off = 4; off; off >>= 1)
                vv += __shfl_xor_sync(0xffffffffu, vv, off);
            if (lane == 0) g_partials[blockIdx.x * 5 + k] = vv;
        }
    }

    // ── last-block final reduction ──
    __shared__ bool isLast;
    if (threadIdx.x == 0) {
        __threadfence();
        unsigned old = atomicAdd(&g_count, 1u);
        isLast = (old == gridDim.x - 1u);
    }
    __syncthreads();
    if (isLast) {
        const volatile float* gp = g_partials;
        float loc[5] = {0.f, 0.f, 0.f, 0.f, 0.f};
        for (int j = threadIdx.x; j < (int)gridDim.x; j += TPB) {
            #pragma unroll
            for (int k = 0; k < 5; k++) loc[k] += gp[j * 5 + k];
        }
        __shared__ float red[TPB];
        float tot[5];
        #pragma unroll
        for (int k = 0; k < 5; k++) {
            red[threadIdx.x] = loc[k];
            __syncthreads();
            for (int st = TPB / 2; st; st >>= 1) {
                if (threadIdx.x < st) red[threadIdx.x] += red[threadIdx.x + st];
                __syncthreads();
            }
            tot[k] = red[0];
            __syncthreads();
        }
        if (threadIdx.x == 0) {
            constexpr float LN2 = 0.69314718055994530942f;
            float cnt   = fmaxf(tot[4], 1.0f);
            float inv_c = 1.0f / cnt;
            out[0] = -LN2 * (tot[0] * inv_obj_div
                             + (tot[1] + tot[2]) * 0.5f * inv_c
                             + tot[3] * inv_c);
            g_count = 0;
        }
    }
}

extern "C" void kernel_launch(void* const* d_in, const int* in_sizes, int n_in,
                              void* d_out, int out_size) {
    const float* x  = (const float*)d_in[0];
    const float* tg = (const float*)d_in[1];
    const int rows  = in_sizes[0] / C;     // B * S
    const int Bn    = rows / S_TOT;        // batch
    const float inv_obj_div = 1.0f / ((float)Bn * (float)S1 * (float)C);
    const unsigned tg_bytes = (unsigned)in_sizes[1] * 4u;

    int dev = 0, smCount = 148, bpm = MINBPM;
    cudaGetDevice(&dev);
    cudaDeviceGetAttribute(&smCount, cudaDevAttrMultiProcessorCount, dev);
    cudaOccupancyMaxActiveBlocksPerMultiprocessor(&bpm, yolo_fused, TPB, 0);
    int nb = smCount * (bpm > 0 ? bpm : 1);
    if (nb > MAXNB) nb = MAXNB;

    yolo_fused<<<nb, TPB>>>(x, tg, Bn, inv_obj_div, tg_bytes, (float*)d_out);
}

// round 15
// speedup vs baseline: 1.0855x; 1.0855x over previous
#include <cuda_runtime.h>

namespace {
constexpr int S_TOT   = 22743;           // 3*(76^2 + 38^2 + 19^2)
constexpr int S1      = 17328;           // 76*76*3
constexpr int C       = 85;
constexpr int LEN     = S1 * C;          // 1,472,880 dense floats per batch
constexpr int STRIDEB = S_TOT * C;       // 1,933,155 floats per batch
constexpr int V4U     = (LEN - 3) / 4;   // 368,219 uniform float4s per batch
constexpr int OFF4_D  = (STRIDEB + 1) / 4;  // 483,289 (pad delta +1)
constexpr int OFF4_D3 = (STRIDEB - 3) / 4;  // 483,288 (pad delta -3, b%4==3)
constexpr int TPB     = 256;
constexpr int MINBPM  = 4;               // 64 regs/thread budget -> real MLP=8
constexpr int MAXNB   = 4096;
constexpr unsigned PRIM_BYTES = 96u << 20;   // 96 MB of tg pinned evict_last
}

__device__ float    g_partials[MAXNB * 5];
__device__ unsigned g_count = 0;

// Range policy: tg[0, prim) -> evict_last, tg[prim, tot) -> evict_first
__device__ __forceinline__ unsigned long long mk_policy_range(const void* base,
                                                              unsigned prim,
                                                              unsigned tot) {
    unsigned long long pol;
    asm("createpolicy.range.global.L2::evict_last.L2::evict_first.b64 %0, [%1], %2, %3;"
        : "=l"(pol) : "l"(base), "r"(prim), "r"(tot));
    return pol;
}

__device__ __forceinline__ float4 ld_el4(const float4* p, unsigned long long pol) {
    float4 v;
    asm("ld.global.nc.L2::cache_hint.v4.f32 {%0,%1,%2,%3}, [%4], %5;"
        : "=f"(v.x), "=f"(v.y), "=f"(v.z), "=f"(v.w) : "l"(p), "l"(pol));
    return v;
}
__device__ __forceinline__ float ld_el1(const float* p, unsigned long long pol) {
    float v;
    asm("ld.global.nc.L2::cache_hint.f32 %0, [%1], %2;" : "=f"(v) : "l"(p), "l"(pol));
    return v;
}

// BCE in log2 units: returns t*(lg2 p - lg2 q) + lg2 q ; final loss = -ln2 * sum
__device__ __forceinline__ float bce_l2(float p, float t) {
    float lp = __log2f(p);
    float lq = __log2f(1.0f - p);
    return fmaf(t, lp - lq, lq);
}

__device__ __forceinline__ float bce4_l2(float4 p, float4 t) {
    float b0 = bce_l2(p.x, t.x);
    float b1 = bce_l2(p.y, t.y);
    float b2 = bce_l2(p.z, t.z);
    float b3 = bce_l2(p.w, t.w);
    return (b0 + b1) + (b2 + b3);
}

__global__ __launch_bounds__(TPB, MINBPM)
void yolo_fused(const float* __restrict__ x,
                const float* __restrict__ tg,
                int B, float inv_obj_div,
                unsigned tg_bytes,
                float* __restrict__ out) {
    const int gtid = blockIdx.x * TPB + threadIdx.x;
    const int NT   = gridDim.x * TPB;
    const int W4   = B * V4U;
    const int rows = B * S_TOT;
    const unsigned long long POL = mk_policy_range(tg, PRIM_BYTES, tg_bytes);

    const float4* __restrict__ x4 = (const float4*)x;
    const float4* __restrict__ t4 = (const float4*)tg;

    float a_obj = 0.f, a_xy = 0.f, a_wh = 0.f, a_cls = 0.f, a_cnt = 0.f;

    // ── Prefetch first two Pass-B probes (held across Pass A) ──
    const int r0 = gtid;
    const int r1 = gtid + NT;
    float pf0 = ld_el1(tg + r0 * C + 4, POL);
    float pf1 = (r1 < rows) ? ld_el1(tg + r1 * C + 4, POL) : 0.0f;

    // ── Pass A: flat dense-slab BCE, batch carried incrementally (no div) ──
    int v = gtid, b = 0, off4 = 0;

#define YSTEP()                                                    \
    do {                                                           \
        v += NT;                                                   \
        if (v >= V4U) {                                            \
            v -= V4U;                                              \
            off4 += ((b & 3) == 3) ? OFF4_D3 : OFF4_D;             \
            ++b;                                                   \
        }                                                          \
    } while (0)

    int w = gtid;
    for (; w + 3 * NT < W4; w += 4 * NT) {
        int a0 = off4 + v; YSTEP();
        int a1 = off4 + v; YSTEP();
        int a2 = off4 + v; YSTEP();
        int a3 = off4 + v; YSTEP();
        // x: streaming/evict-first; tg: range policy (96MB pinned evict_last)
        float4 p0 = __ldcs(x4 + a0), q0 = ld_el4(t4 + a0, POL);
        float4 p1 = __ldcs(x4 + a1), q1 = ld_el4(t4 + a1, POL);
        float4 p2 = __ldcs(x4 + a2), q2 = ld_el4(t4 + a2, POL);
        float4 p3 = __ldcs(x4 + a3), q3 = ld_el4(t4 + a3, POL);
        a_obj += bce4_l2(p0, q0) + bce4_l2(p1, q1);
        a_obj += bce4_l2(p2, q2) + bce4_l2(p3, q3);
    }
    for (; w < W4; w += NT) {
        int a0 = off4 + v; YSTEP();
        a_obj += bce4_l2(__ldcs(x4 + a0), ld_el4(t4 + a0, POL));
    }
#undef YSTEP

    // Third-row probe: issued now, consumed after leftover handling.
    const int r2 = gtid + 2 * NT;
    float pf2 = (r2 < rows) ? ld_el1(tg + r2 * C + 4, POL) : 0.0f;

    // leftover scalars: exactly 4 per batch (alignment head + tail remainder)
    if (gtid < 4 * B) {
        int bb  = gtid >> 2, j = gtid & 3;
        int pad = bb & 3;
        int base = bb * STRIDEB;
        int idx = (j < pad) ? (base + j)
                            : (base + pad + 4 * V4U + (j - pad));
        a_obj += bce_l2(x[idx], ld_el1(tg + idx, POL));
    }

    // ── Pass B: gated xy/wh/cls terms ──
    {
        if (pf0 > 0.0f) {
            const int rb = r0 * C;
            a_xy  += bce_l2(__ldg(x + rb + 0), ld_el1(tg + rb + 0, POL))
                   + bce_l2(__ldg(x + rb + 1), ld_el1(tg + rb + 1, POL));
            a_wh  += bce_l2(__ldg(x + rb + 2), ld_el1(tg + rb + 2, POL))
                   + bce_l2(__ldg(x + rb + 3), ld_el1(tg + rb + 3, POL));
            a_cls += bce_l2(__ldg(x + rb + 4), pf0);
            a_cnt += 1.0f;
        }
        if (r1 < rows && pf1 > 0.0f) {
            const int rb = r1 * C;
            a_xy  += bce_l2(__ldg(x + rb + 0), ld_el1(tg + rb + 0, POL))
                   + bce_l2(__ldg(x + rb + 1), ld_el1(tg + rb + 1, POL));
            a_wh  += bce_l2(__ldg(x + rb + 2), ld_el1(tg + rb + 2, POL))
                   + bce_l2(__ldg(x + rb + 3), ld_el1(tg + rb + 3, POL));
            a_cls += bce_l2(__ldg(x + rb + 4), pf1);
            a_cnt += 1.0f;
        }
        if (r2 < rows && pf2 > 0.0f) {
            const int rb = r2 * C;
            a_xy  += bce_l2(__ldg(x + rb + 0), ld_el1(tg + rb + 0, POL))
                   + bce_l2(__ldg(x + rb + 1), ld_el1(tg + rb + 1, POL));
            a_wh  += bce_l2(__ldg(x + rb + 2), ld_el1(tg + rb + 2, POL))
                   + bce_l2(__ldg(x + rb + 3), ld_el1(tg + rb + 3, POL));
            a_cls += bce_l2(__ldg(x + rb + 4), pf2);
            a_cnt += 1.0f;
        }
        // safety remainder (only if the grid ended up tiny)
        for (int r = gtid + 3 * NT; r < rows; r += NT) {
            const int rb = r * C;
            float t4v = ld_el1(tg + rb + 4, POL);
            if (t4v > 0.0f) {
                a_xy  += bce_l2(x[rb + 0], ld_el1(tg + rb + 0, POL))
                       + bce_l2(x[rb + 1], ld_el1(tg + rb + 1, POL));
                a_wh  += bce_l2(x[rb + 2], ld_el1(tg + rb + 2, POL))
                       + bce_l2(x[rb + 3], ld_el1(tg + rb + 3, POL));
                a_cls += bce_l2(x[rb + 4], t4v);
                a_cnt += 1.0f;
            }
        }
    }

    // ── block reduction (5 scalars) ──
    const int lane = threadIdx.x & 31;
    const int wid  = threadIdx.x >> 5;
    #pragma unroll
    for (int off = 16; off; off >>= 1) {
        a_obj += __shfl_xor_sync(0xffffffffu, a_obj, off);
        a_xy  += __shfl_xor_sync(0xffffffffu, a_xy,  off);
        a_wh  += __shfl_xor_sync(0xffffffffu, a_wh,  off);
        a_cls += __shfl_xor_sync(0xffffffffu, a_cls, off);
        a_cnt += __shfl_xor_sync(0xffffffffu, a_cnt, off);
    }
    __shared__ float sm[TPB / 32][5];
    if (lane == 0) {
        sm[wid][0] = a_obj; sm[wid][1] = a_xy; sm[wid][2] = a_wh;
        sm[wid][3] = a_cls; sm[wid][4] = a_cnt;
    }
    __syncthreads();
    if (threadIdx.x < 32) {
        #pragma unroll
        for (int k = 0; k < 5; k++) {
            float vv = (lane < TPB / 32) ? sm[lane][k] : 0.0f;
            #pragma unroll
            for (int off = 4; off; off >>= 1)
                vv += __shfl_xor_sync(0xffffffffu, vv, off);
            if (lane == 0) g_partials[blockIdx.x * 5 + k] = vv;
        }
    }

    // ── last-block final reduction ──
    __shared__ bool isLast;
    if (threadIdx.x == 0) {
        __threadfence();
        unsigned old = atomicAdd(&g_count, 1u);
        isLast = (old == gridDim.x - 1u);
    }
    __syncthreads();
    if (isLast) {
        const volatile float* gp = g_partials;
        float loc[5] = {0.f, 0.f, 0.f, 0.f, 0.f};
        for (int j = threadIdx.x; j < (int)gridDim.x; j += TPB) {
            #pragma unroll
            for (int k = 0; k < 5; k++) loc[k] += gp[j * 5 + k];
        }
        __shared__ float red[TPB];
        float tot[5];
        #pragma unroll
        for (int k = 0; k < 5; k++) {
            red[threadIdx.x] = loc[k];
            __syncthreads();
            for (int st = TPB / 2; st; st >>= 1) {
                if (threadIdx.x < st) red[threadIdx.x] += red[threadIdx.x + st];
                __syncthreads();
            }
            tot[k] = red[0];
            __syncthreads();
        }
        if (threadIdx.x == 0) {
            constexpr float LN2 = 0.69314718055994530942f;
            float cnt   = fmaxf(tot[4], 1.0f);
            float inv_c = 1.0f / cnt;
            out[0] = -LN2 * (tot[0] * inv_obj_div
                             + (tot[1] + tot[2]) * 0.5f * inv_c
                             + tot[3] * inv_c);
            g_count = 0;
        }
    }
}

extern "C" void kernel_launch(void* const* d_in, const int* in_sizes, int n_in,
                              void* d_out, int out_size) {
    const float* x  = (const float*)d_in[0];
    const float* tg = (const float*)d_in[1];
    const int rows  = in_sizes[0] / C;     // B * S
    const int Bn    = rows / S_TOT;        // batch
    const float inv_obj_div = 1.0f / ((float)Bn * (float)S1 * (float)C);
    const unsigned tg_bytes = (unsigned)in_sizes[1] * 4u;

    int dev = 0, smCount = 148, bpm = MINBPM;
    cudaGetDevice(&dev);
    cudaDeviceGetAttribute(&smCount, cudaDevAttrMultiProcessorCount, dev);
    cudaOccupancyMaxActiveBlocksPerMultiprocessor(&bpm, yolo_fused, TPB, 0);
    int nb = smCount * (bpm > 0 ? bpm : 1);
    if (nb > MAXNB) nb = MAXNB;

    yolo_fused<<<nb, TPB>>>(x, tg, Bn, inv_obj_div, tg_bytes, (float*)d_out);
}

// round 16
// speedup vs baseline: 1.1220x; 1.0335x over previous
#include <cuda_runtime.h>

namespace {
constexpr int S_TOT   = 22743;           // 3*(76^2 + 38^2 + 19^2)
constexpr int S1      = 17328;           // 76*76*3
constexpr int C       = 85;
constexpr int LEN     = S1 * C;          // 1,472,880 dense floats per batch
constexpr int STRIDEB = S_TOT * C;       // 1,933,155 floats per batch
constexpr int V4U     = (LEN - 3) / 4;   // 368,219 uniform float4s per batch
constexpr int OFF4_D  = (STRIDEB + 1) / 4;  // 483,289 (pad delta +1)
constexpr int OFF4_D3 = (STRIDEB - 3) / 4;  // 483,288 (pad delta -3, b%4==3)
constexpr int TPB     = 256;
constexpr int MINBPM  = 4;               // 64 regs/thread budget -> real MLP=8
constexpr unsigned PRIM_BYTES = 96u << 20;   // 96 MB of tg pinned evict_last
}

// 5 global accumulators {obj, xy, wh, cls, cnt}; zeroed at load, reset by the
// last block each launch (so every graph replay starts from zero).
__device__ float    g_sums[5] = {0.f, 0.f, 0.f, 0.f, 0.f};
__device__ unsigned g_count   = 0;

// Range policy: tg[0, prim) -> evict_last, tg[prim, tot) -> evict_first
__device__ __forceinline__ unsigned long long mk_policy_range(const void* base,
                                                              unsigned prim,
                                                              unsigned tot) {
    unsigned long long pol;
    asm("createpolicy.range.global.L2::evict_last.L2::evict_first.b64 %0, [%1], %2, %3;"
        : "=l"(pol) : "l"(base), "r"(prim), "r"(tot));
    return pol;
}

__device__ __forceinline__ float4 ld_el4(const float4* p, unsigned long long pol) {
    float4 v;
    asm("ld.global.nc.L2::cache_hint.v4.f32 {%0,%1,%2,%3}, [%4], %5;"
        : "=f"(v.x), "=f"(v.y), "=f"(v.z), "=f"(v.w) : "l"(p), "l"(pol));
    return v;
}
__device__ __forceinline__ float ld_el1(const float* p, unsigned long long pol) {
    float v;
    asm("ld.global.nc.L2::cache_hint.f32 %0, [%1], %2;" : "=f"(v) : "l"(p), "l"(pol));
    return v;
}

// BCE in log2 units: returns t*(lg2 p - lg2 q) + lg2 q ; final loss = -ln2 * sum
__device__ __forceinline__ float bce_l2(float p, float t) {
    float lp = __log2f(p);
    float lq = __log2f(1.0f - p);
    return fmaf(t, lp - lq, lq);
}

__device__ __forceinline__ float bce4_l2(float4 p, float4 t) {
    float b0 = bce_l2(p.x, t.x);
    float b1 = bce_l2(p.y, t.y);
    float b2 = bce_l2(p.z, t.z);
    float b3 = bce_l2(p.w, t.w);
    return (b0 + b1) + (b2 + b3);
}

__global__ __launch_bounds__(TPB, MINBPM)
void yolo_fused(const float* __restrict__ x,
                const float* __restrict__ tg,
                int B, float inv_obj_div,
                unsigned tg_bytes,
                float* __restrict__ out) {
    const int gtid = blockIdx.x * TPB + threadIdx.x;
    const int NT   = gridDim.x * TPB;
    const int W4   = B * V4U;
    const int rows = B * S_TOT;
    const unsigned long long POL = mk_policy_range(tg, PRIM_BYTES, tg_bytes);

    const float4* __restrict__ x4 = (const float4*)x;
    const float4* __restrict__ t4 = (const float4*)tg;

    float a_obj = 0.f, a_xy = 0.f, a_wh = 0.f, a_cls = 0.f, a_cnt = 0.f;

    // ── Prefetch first two Pass-B probes (held across Pass A) ──
    const int r0 = gtid;
    const int r1 = gtid + NT;
    float pf0 = ld_el1(tg + r0 * C + 4, POL);
    float pf1 = (r1 < rows) ? ld_el1(tg + r1 * C + 4, POL) : 0.0f;

    // ── Pass A: flat dense-slab BCE, batch carried incrementally (no div) ──
    int v = gtid, b = 0, off4 = 0;

#define YSTEP()                                                    \
    do {                                                           \
        v += NT;                                                   \
        if (v >= V4U) {                                            \
            v -= V4U;                                              \
            off4 += ((b & 3) == 3) ? OFF4_D3 : OFF4_D;             \
            ++b;                                                   \
        }                                                          \
    } while (0)

    int w = gtid;
    for (; w + 3 * NT < W4; w += 4 * NT) {
        int a0 = off4 + v; YSTEP();
        int a1 = off4 + v; YSTEP();
        int a2 = off4 + v; YSTEP();
        int a3 = off4 + v; YSTEP();
        // x: streaming/evict-first; tg: range policy (96MB pinned evict_last)
        float4 p0 = __ldcs(x4 + a0), q0 = ld_el4(t4 + a0, POL);
        float4 p1 = __ldcs(x4 + a1), q1 = ld_el4(t4 + a1, POL);
        float4 p2 = __ldcs(x4 + a2), q2 = ld_el4(t4 + a2, POL);
        float4 p3 = __ldcs(x4 + a3), q3 = ld_el4(t4 + a3, POL);
        a_obj += bce4_l2(p0, q0) + bce4_l2(p1, q1);
        a_obj += bce4_l2(p2, q2) + bce4_l2(p3, q3);
    }
    for (; w < W4; w += NT) {
        int a0 = off4 + v; YSTEP();
        a_obj += bce4_l2(__ldcs(x4 + a0), ld_el4(t4 + a0, POL));
    }
#undef YSTEP

    // Third-row probe: issued now, consumed after leftover handling.
    const int r2 = gtid + 2 * NT;
    float pf2 = (r2 < rows) ? ld_el1(tg + r2 * C + 4, POL) : 0.0f;

    // leftover scalars: exactly 4 per batch (alignment head + tail remainder)
    if (gtid < 4 * B) {
        int bb  = gtid >> 2, j = gtid & 3;
        int pad = bb & 3;
        int base = bb * STRIDEB;
        int idx = (j < pad) ? (base + j)
                            : (base + pad + 4 * V4U + (j - pad));
        a_obj += bce_l2(x[idx], ld_el1(tg + idx, POL));
    }

    // ── Pass B: gated xy/wh/cls terms ──
    {
        if (pf0 > 0.0f) {
            const int rb = r0 * C;
            a_xy  += bce_l2(__ldg(x + rb + 0), ld_el1(tg + rb + 0, POL))
                   + bce_l2(__ldg(x + rb + 1), ld_el1(tg + rb + 1, POL));
            a_wh  += bce_l2(__ldg(x + rb + 2), ld_el1(tg + rb + 2, POL))
                   + bce_l2(__ldg(x + rb + 3), ld_el1(tg + rb + 3, POL));
            a_cls += bce_l2(__ldg(x + rb + 4), pf0);
            a_cnt += 1.0f;
        }
        if (r1 < rows && pf1 > 0.0f) {
            const int rb = r1 * C;
            a_xy  += bce_l2(__ldg(x + rb + 0), ld_el1(tg + rb + 0, POL))
                   + bce_l2(__ldg(x + rb + 1), ld_el1(tg + rb + 1, POL));
            a_wh  += bce_l2(__ldg(x + rb + 2), ld_el1(tg + rb + 2, POL))
                   + bce_l2(__ldg(x + rb + 3), ld_el1(tg + rb + 3, POL));
            a_cls += bce_l2(__ldg(x + rb + 4), pf1);
            a_cnt += 1.0f;
        }
        if (r2 < rows && pf2 > 0.0f) {
            const int rb = r2 * C;
            a_xy  += bce_l2(__ldg(x + rb + 0), ld_el1(tg + rb + 0, POL))
                   + bce_l2(__ldg(x + rb + 1), ld_el1(tg + rb + 1, POL));
            a_wh  += bce_l2(__ldg(x + rb + 2), ld_el1(tg + rb + 2, POL))
                   + bce_l2(__ldg(x + rb + 3), ld_el1(tg + rb + 3, POL));
            a_cls += bce_l2(__ldg(x + rb + 4), pf2);
            a_cnt += 1.0f;
        }
        // safety remainder (only if the grid ended up tiny)
        for (int r = gtid + 3 * NT; r < rows; r += NT) {
            const int rb = r * C;
            float t4v = ld_el1(tg + rb + 4, POL);
            if (t4v > 0.0f) {
                a_xy  += bce_l2(x[rb + 0], ld_el1(tg + rb + 0, POL))
                       + bce_l2(x[rb + 1], ld_el1(tg + rb + 1, POL));
                a_wh  += bce_l2(x[rb + 2], ld_el1(tg + rb + 2, POL))
                       + bce_l2(x[rb + 3], ld_el1(tg + rb + 3, POL));
                a_cls += bce_l2(x[rb + 4], t4v);
                a_cnt += 1.0f;
            }
        }
    }

    // ── block reduction (5 scalars) ──
    const int lane = threadIdx.x & 31;
    const int wid  = threadIdx.x >> 5;
    #pragma unroll
    for (int off = 16; off; off >>= 1) {
        a_obj += __shfl_xor_sync(0xffffffffu, a_obj, off);
        a_xy  += __shfl_xor_sync(0xffffffffu, a_xy,  off);
        a_wh  += __shfl_xor_sync(0xffffffffu, a_wh,  off);
        a_cls += __shfl_xor_sync(0xffffffffu, a_cls, off);
        a_cnt += __shfl_xor_sync(0xffffffffu, a_cnt, off);
    }
    __shared__ float sm[TPB / 32][5];
    if (lane == 0) {
        sm[wid][0] = a_obj; sm[wid][1] = a_xy; sm[wid][2] = a_wh;
        sm[wid][3] = a_cls; sm[wid][4] = a_cnt;
    }
    __syncthreads();
    if (threadIdx.x < 32) {
        #pragma unroll
        for (int k = 0; k < 5; k++) {
            float vv = (lane < TPB / 32) ? sm[lane][k] : 0.0f;
            #pragma unroll
            for (int off = 4; off; off >>= 1)
                vv += __shfl_xor_sync(0xffffffffu, vv, off);
            // fire-and-forget global accumulation (REDG); overlaps with
            // other blocks still streaming Pass A
            if (lane == 0) atomicAdd(&g_sums[k], vv);
        }
    }

    // ── last-block finalization (tiny: 5 loads + 4 FMA + 1 store) ──
    __shared__ bool isLast;
    if (threadIdx.x == 0) {
        __threadfence();                       // publish our g_sums adds
        unsigned old = atomicAdd(&g_count, 1u);
        isLast = (old == gridDim.x - 1u);
    }
    __syncthreads();
    if (isLast && threadIdx.x == 0) {
        volatile float* gs = g_sums;
        float t_obj = gs[0], t_xy = gs[1], t_wh = gs[2];
        float t_cls = gs[3], t_cnt = gs[4];
        constexpr float LN2 = 0.69314718055994530942f;
        float cnt   = fmaxf(t_cnt, 1.0f);
        float inv_c = 1.0f / cnt;
        out[0] = -LN2 * (t_obj * inv_obj_div
                         + (t_xy + t_wh) * 0.5f * inv_c
                         + t_cls * inv_c);
        // reset for the next graph replay
        gs[0] = 0.f; gs[1] = 0.f; gs[2] = 0.f; gs[3] = 0.f; gs[4] = 0.f;
        g_count = 0;
    }
}

extern "C" void kernel_launch(void* const* d_in, const int* in_sizes, int n_in,
                              void* d_out, int out_size) {
    const float* x  = (const float*)d_in[0];
    const float* tg = (const float*)d_in[1];
    const int rows  = in_sizes[0] / C;     // B * S
    const int Bn    = rows / S_TOT;        // batch
    const float inv_obj_div = 1.0f / ((float)Bn * (float)S1 * (float)C);
    const unsigned tg_bytes = (unsigned)in_sizes[1] * 4u;

    int dev = 0, smCount = 148, bpm = MINBPM;
    cudaGetDevice(&dev);
    cudaDeviceGetAttribute(&smCount, cudaDevAttrMultiProcessorCount, dev);
    cudaOccupancyMaxActiveBlocksPerMultiprocessor(&bpm, yolo_fused, TPB, 0);
    int nb = smCount * (bpm > 0 ? bpm : 1);

    yolo_fused<<<nb, TPB>>>(x, tg, Bn, inv_obj_div, tg_bytes, (float*)d_out);
}